// round 6
// baseline (speedup 1.0000x reference)
#include <cuda_runtime.h>
#include <cuda_bf16.h>
#include <math.h>
#include <stdint.h>

#define D 256
#define BATCH 64
#define NTOK 4096
#define S 8
#define ROWS_BIG (BATCH * NTOK)   // 262144
#define ROWS_SLOT (BATCH * S)     // 512
#define PRED 8                    // partials per batch after in-CTA reduce

// ---------------- scratch (device globals; no allocations allowed) ----------
__device__ __nv_bfloat16 g_xln16[(size_t)ROWS_BIG * D];   // 134 MB
__device__ __nv_bfloat16 g_k16[(size_t)ROWS_BIG * D];     // 134 MB
__device__ __nv_bfloat16 g_v16[(size_t)ROWS_BIG * D];     // 134 MB
__device__ __nv_bfloat16 g_w16[2 * D * D];                // concat(Wk, Wv) [512,256]
__device__ float g_bias[2 * D];                           // concat(bk, bv)
__device__ float g_slots[ROWS_SLOT * D];
__device__ float g_slots2[ROWS_SLOT * D];
__device__ float g_qbuf[ROWS_SLOT * D];
__device__ float g_upd[ROWS_SLOT * D];
__device__ float g_pnum[(size_t)BATCH * PRED * S * D];    // 4.2 MB
__device__ float g_pden[BATCH * PRED * S];

// ---------------- PTX helpers (arch-agnostic: sm_80+ features only) ----------
__device__ __forceinline__ uint32_t smem_u32(const void* p) {
    uint32_t a;
    asm("{ .reg .u64 t; cvta.to.shared.u64 t, %1; cvt.u32.u64 %0, t; }" : "=r"(a) : "l"(p));
    return a;
}
__device__ __forceinline__ void cpasync16(uint32_t saddr, const void* g) {
    asm volatile("cp.async.cg.shared.global [%0], [%1], 16;" :: "r"(saddr), "l"(g));
}
#define CP_COMMIT() asm volatile("cp.async.commit_group;" ::: "memory")
#define CP_WAIT(n)  asm volatile("cp.async.wait_group %0;" :: "n"(n) : "memory")

__device__ __forceinline__ void ldsm_x4(uint32_t& r0, uint32_t& r1, uint32_t& r2, uint32_t& r3,
                                        uint32_t addr) {
    asm volatile("ldmatrix.sync.aligned.m8n8.x4.shared.b16 {%0,%1,%2,%3}, [%4];"
                 : "=r"(r0), "=r"(r1), "=r"(r2), "=r"(r3) : "r"(addr));
}
__device__ __forceinline__ void mma16816(float* d, const uint32_t* a, const uint32_t* b) {
    asm volatile("mma.sync.aligned.m16n8k16.row.col.f32.bf16.bf16.f32 "
                 "{%0,%1,%2,%3}, {%4,%5,%6,%7}, {%8,%9}, {%0,%1,%2,%3};"
                 : "+f"(d[0]), "+f"(d[1]), "+f"(d[2]), "+f"(d[3])
                 : "r"(a[0]), "r"(a[1]), "r"(a[2]), "r"(a[3]), "r"(b[0]), "r"(b[1]));
}
__device__ __forceinline__ float2 bf2f(uint32_t u) {
    __nv_bfloat162 h = *reinterpret_cast<__nv_bfloat162*>(&u);
    return __bfloat1622float2(h);
}

// ---------------- weights fp32 -> bf16 (concat layout) -----------------------
__global__ void conv_w_kernel(const float* __restrict__ wk, const float* __restrict__ wv,
                              const float* __restrict__ bk, const float* __restrict__ bv,
                              __nv_bfloat16* __restrict__ w16, float* __restrict__ bias)
{
    int i = blockIdx.x * 256 + threadIdx.x;   // 0..65535
    w16[i]             = __float2bfloat16(wk[i]);
    w16[i + D * D]     = __float2bfloat16(wv[i]);
    if (i < D) { bias[i] = bk[i]; bias[i + D] = bv[i]; }
}

// ---------------- LayerNorm fp32 -> bf16 (big input) -------------------------
__global__ void ln_rows_bf16_kernel(const float* __restrict__ in, __nv_bfloat16* __restrict__ out,
                                    const float* __restrict__ gamma, const float* __restrict__ beta)
{
    int gw   = (blockIdx.x * blockDim.x + threadIdx.x) >> 5;
    int lane = threadIdx.x & 31;
    const float* row = in + (size_t)gw * D;
    float4 a = *(const float4*)(row + lane * 4);
    float4 b = *(const float4*)(row + 128 + lane * 4);
    float s  = a.x + a.y + a.z + a.w + b.x + b.y + b.z + b.w;
    float s2 = a.x*a.x + a.y*a.y + a.z*a.z + a.w*a.w
             + b.x*b.x + b.y*b.y + b.z*b.z + b.w*b.w;
#pragma unroll
    for (int off = 16; off; off >>= 1) {
        s  += __shfl_xor_sync(0xffffffffu, s,  off);
        s2 += __shfl_xor_sync(0xffffffffu, s2, off);
    }
    float mean = s * (1.0f / 256.0f);
    float var  = s2 * (1.0f / 256.0f) - mean * mean;
    float rstd = rsqrtf(var + 1e-5f);
    float4 g0 = *(const float4*)(gamma + lane * 4);
    float4 g1 = *(const float4*)(gamma + 128 + lane * 4);
    float4 e0 = *(const float4*)(beta + lane * 4);
    float4 e1 = *(const float4*)(beta + 128 + lane * 4);
    __nv_bfloat162 p[4];
    p[0] = __float22bfloat162_rn(make_float2((a.x - mean) * rstd * g0.x + e0.x,
                                             (a.y - mean) * rstd * g0.y + e0.y));
    p[1] = __float22bfloat162_rn(make_float2((a.z - mean) * rstd * g0.z + e0.z,
                                             (a.w - mean) * rstd * g0.w + e0.w));
    p[2] = __float22bfloat162_rn(make_float2((b.x - mean) * rstd * g1.x + e1.x,
                                             (b.y - mean) * rstd * g1.y + e1.y));
    p[3] = __float22bfloat162_rn(make_float2((b.z - mean) * rstd * g1.z + e1.z,
                                             (b.w - mean) * rstd * g1.w + e1.w));
    __nv_bfloat16* o = out + (size_t)gw * D;
    *(uint2*)(o + lane * 4)       = make_uint2(*(uint32_t*)&p[0], *(uint32_t*)&p[1]);
    *(uint2*)(o + 128 + lane * 4) = make_uint2(*(uint32_t*)&p[2], *(uint32_t*)&p[3]);
}

// ---------------- KV projection: bf16 mma.sync GEMM --------------------------
#define BMT 128
#define BNT 128
#define KV_STAGE 16384
#define KV_SMEM  (4 * KV_STAGE)        // 64 KB

__global__ void __launch_bounds__(256, 2) kv_mma_kernel(
    const __nv_bfloat16* __restrict__ A,
    const __nv_bfloat16* __restrict__ W,
    const float* __restrict__ bias,
    __nv_bfloat16* __restrict__ Kout,
    __nv_bfloat16* __restrict__ Vout)
{
    extern __shared__ char smem[];
    const int tid  = threadIdx.x;
    const int lane = tid & 31;
    const int wid  = tid >> 5;
    const int wm   = wid >> 1;
    const int wn   = wid & 1;
    const int bm   = blockIdx.y * BMT;
    const int bn   = blockIdx.x * BNT;
    const uint32_t sb = smem_u32(smem);

    const char* Ag = (const char*)A + (size_t)bm * 512;
    const char* Wg = (const char*)W + (size_t)bn * 512;

    float acc[2][8][4];
#pragma unroll
    for (int mi = 0; mi < 2; mi++)
#pragma unroll
        for (int nj = 0; nj < 8; nj++)
#pragma unroll
            for (int x = 0; x < 4; x++) acc[mi][nj][x] = 0.0f;

#define LOAD_STAGE(kb, st) do {                                               \
        uint32_t abase = sb + (st) * 2 * KV_STAGE;                            \
        uint32_t bbase = abase + KV_STAGE;                                    \
        const char* ag = Ag + (kb) * 128;                                     \
        const char* wg = Wg + (kb) * 128;                                     \
        _Pragma("unroll")                                                     \
        for (int i = 0; i < 4; i++) {                                         \
            int ci = tid + i * 256;                                           \
            int r = ci >> 3, c = ci & 7;                                      \
            cpasync16(abase + r * 128 + ((c ^ (r & 7)) * 16),                 \
                      ag + (size_t)r * 512 + c * 16);                         \
        }                                                                     \
        _Pragma("unroll")                                                     \
        for (int i = 0; i < 4; i++) {                                         \
            int ci = tid + i * 256;                                           \
            int r = ci >> 3, c = ci & 7;                                      \
            cpasync16(bbase + r * 128 + ((c ^ (r & 7)) * 16),                 \
                      wg + (size_t)r * 512 + c * 16);                         \
        }                                                                     \
        CP_COMMIT();                                                          \
    } while (0)

    LOAD_STAGE(0, 0);

#pragma unroll 1
    for (int kb = 0; kb < 4; kb++) {
        if (kb < 3) { LOAD_STAGE(kb + 1, (kb + 1) & 1); CP_WAIT(1); }
        else        { CP_WAIT(0); }
        __syncthreads();

        uint32_t abase = sb + (kb & 1) * 2 * KV_STAGE;
        uint32_t bbase = abase + KV_STAGE;
#pragma unroll
        for (int ks = 0; ks < 4; ks++) {
            uint32_t afr[2][4];
#pragma unroll
            for (int mi = 0; mi < 2; mi++) {
                int row   = wm * 32 + mi * 16 + (lane & 15);
                int chunk = (ks * 2 + (lane >> 4)) ^ (row & 7);
                ldsm_x4(afr[mi][0], afr[mi][1], afr[mi][2], afr[mi][3],
                        abase + row * 128 + chunk * 16);
            }
            uint32_t bfr[8][2];
#pragma unroll
            for (int njp = 0; njp < 4; njp++) {
                int row   = wn * 64 + njp * 16 + ((lane >> 4) & 1) * 8 + (lane & 7);
                int chunk = (ks * 2 + ((lane >> 3) & 1)) ^ (row & 7);
                uint32_t r0, r1, r2, r3;
                ldsm_x4(r0, r1, r2, r3, bbase + row * 128 + chunk * 16);
                bfr[njp * 2][0]     = r0; bfr[njp * 2][1]     = r1;
                bfr[njp * 2 + 1][0] = r2; bfr[njp * 2 + 1][1] = r3;
            }
#pragma unroll
            for (int mi = 0; mi < 2; mi++)
#pragma unroll
                for (int nj = 0; nj < 8; nj++)
                    mma16816(acc[mi][nj], afr[mi], bfr[nj]);
        }
        __syncthreads();
    }

    __nv_bfloat16* outp;
    int cb;
    if (bn < 256) { outp = Kout; cb = bn; } else { outp = Vout; cb = bn - 256; }
#pragma unroll
    for (int mi = 0; mi < 2; mi++) {
        int r0 = bm + wm * 32 + mi * 16 + (lane >> 2);
#pragma unroll
        for (int nj = 0; nj < 8; nj++) {
            int ncol = wn * 64 + nj * 8 + (lane & 3) * 2;
            float2 bs = *(const float2*)&bias[bn + ncol];
            __nv_bfloat162 lo = __float22bfloat162_rn(
                make_float2(acc[mi][nj][0] + bs.x, acc[mi][nj][1] + bs.y));
            __nv_bfloat162 hi = __float22bfloat162_rn(
                make_float2(acc[mi][nj][2] + bs.x, acc[mi][nj][3] + bs.y));
            *(__nv_bfloat162*)(outp + (size_t)r0 * D + cb + ncol)       = lo;
            *(__nv_bfloat162*)(outp + (size_t)(r0 + 8) * D + cb + ncol) = hi;
        }
    }
#undef LOAD_STAGE
}

// ---------------- slot_pre: LN(slots) + q = sn@wq^T + bq ---------------------
// one CTA per batch, 256 threads; 8 warps do 8 LN rows, then GEMM from smem
__global__ void __launch_bounds__(256) slot_pre_kernel(
    const float* __restrict__ slots, const float* __restrict__ wq,
    const float* __restrict__ bq, const float* __restrict__ gsl,
    const float* __restrict__ bsl, float* __restrict__ qout)
{
    __shared__ float sn[S][D];
    const int b    = blockIdx.x;
    const int tid  = threadIdx.x;
    const int wid  = tid >> 5;
    const int lane = tid & 31;

    {   // LN row wid
        const float* row = slots + ((size_t)b * S + wid) * D;
        float4 a = *(const float4*)(row + lane * 4);
        float4 c = *(const float4*)(row + 128 + lane * 4);
        float s  = a.x + a.y + a.z + a.w + c.x + c.y + c.z + c.w;
        float s2 = a.x*a.x + a.y*a.y + a.z*a.z + a.w*a.w
                 + c.x*c.x + c.y*c.y + c.z*c.z + c.w*c.w;
#pragma unroll
        for (int off = 16; off; off >>= 1) {
            s  += __shfl_xor_sync(0xffffffffu, s,  off);
            s2 += __shfl_xor_sync(0xffffffffu, s2, off);
        }
        float mean = s * (1.0f / 256.0f);
        float rstd = rsqrtf(s2 * (1.0f / 256.0f) - mean * mean + 1e-5f);
        float4 g0 = *(const float4*)(gsl + lane * 4);
        float4 g1 = *(const float4*)(gsl + 128 + lane * 4);
        float4 e0 = *(const float4*)(bsl + lane * 4);
        float4 e1 = *(const float4*)(bsl + 128 + lane * 4);
        sn[wid][lane * 4 + 0] = (a.x - mean) * rstd * g0.x + e0.x;
        sn[wid][lane * 4 + 1] = (a.y - mean) * rstd * g0.y + e0.y;
        sn[wid][lane * 4 + 2] = (a.z - mean) * rstd * g0.z + e0.z;
        sn[wid][lane * 4 + 3] = (a.w - mean) * rstd * g0.w + e0.w;
        sn[wid][128 + lane * 4 + 0] = (c.x - mean) * rstd * g1.x + e1.x;
        sn[wid][128 + lane * 4 + 1] = (c.y - mean) * rstd * g1.y + e1.y;
        sn[wid][128 + lane * 4 + 2] = (c.z - mean) * rstd * g1.z + e1.z;
        sn[wid][128 + lane * 4 + 3] = (c.w - mean) * rstd * g1.w + e1.w;
    }
    __syncthreads();

    // q[i][tid] for i=0..7
    float acc[S];
#pragma unroll
    for (int i = 0; i < S; i++) acc[i] = 0.0f;
    const float* wrow = wq + (size_t)tid * D;
#pragma unroll 4
    for (int k = 0; k < D; k += 4) {
        float4 w4 = *(const float4*)(wrow + k);
#pragma unroll
        for (int i = 0; i < S; i++) {
            float4 s4 = *(const float4*)&sn[i][k];
            acc[i] += s4.x * w4.x + s4.y * w4.y + s4.z * w4.z + s4.w * w4.w;
        }
    }
    float bb = bq[tid];
    float* qo = qout + (size_t)b * S * D;
#pragma unroll
    for (int i = 0; i < S; i++) qo[i * D + tid] = acc[i] + bb;
}

// ---------------- Fused attention pass (bf16 k/v, in-CTA reduce) -------------
__global__ void __launch_bounds__(256) attn_pass_kernel(
    const float* __restrict__ q,
    const __nv_bfloat16* __restrict__ k,
    const __nv_bfloat16* __restrict__ v,
    float* __restrict__ pnum,
    float* __restrict__ pden)
{
    extern __shared__ float sred[];          // 8*2048 floats + 64 den
    const int b    = blockIdx.y;
    const int wid  = threadIdx.x >> 5;
    const int lane = threadIdx.x & 31;
    const int tid  = threadIdx.x;
    const int wg   = blockIdx.x * 8 + wid;   // 0..63
    const float scale = 0.0625f;

    float qr[8][8];
    const float* qb = q + b * S * D;
#pragma unroll
    for (int i = 0; i < 8; i++) {
        float4 q0 = *(const float4*)(qb + i * D + lane * 8);
        float4 q1 = *(const float4*)(qb + i * D + lane * 8 + 4);
        qr[i][0] = q0.x * scale; qr[i][1] = q0.y * scale;
        qr[i][2] = q0.z * scale; qr[i][3] = q0.w * scale;
        qr[i][4] = q1.x * scale; qr[i][5] = q1.y * scale;
        qr[i][6] = q1.z * scale; qr[i][7] = q1.w * scale;
    }

    float acc[8][8];
#pragma unroll
    for (int i = 0; i < 8; i++)
#pragma unroll
        for (int j = 0; j < 8; j++) acc[i][j] = 0.0f;
    float den[8] = {0, 0, 0, 0, 0, 0, 0, 0};

    const size_t base = (size_t)b * NTOK * D;
    const __nv_bfloat16* kb = k + base;
    const __nv_bfloat16* vb = v + base;

    int n = wg;
    uint4 ku = *(const uint4*)(kb + (size_t)n * D + lane * 8);
    uint4 vu = *(const uint4*)(vb + (size_t)n * D + lane * 8);

#pragma unroll 1
    for (int t = 0; t < 64; t++) {
        uint4 nku = ku, nvu = vu;
        int nn = n + 64;
        if (t < 63) {
            nku = *(const uint4*)(kb + (size_t)nn * D + lane * 8);
            nvu = *(const uint4*)(vb + (size_t)nn * D + lane * 8);
        }

        float kx[8];
        { float2 f;
          f = bf2f(ku.x); kx[0] = f.x; kx[1] = f.y;
          f = bf2f(ku.y); kx[2] = f.x; kx[3] = f.y;
          f = bf2f(ku.z); kx[4] = f.x; kx[5] = f.y;
          f = bf2f(ku.w); kx[6] = f.x; kx[7] = f.y; }

        float dot[8];
#pragma unroll
        for (int i = 0; i < 8; i++) {
            float d0 = 0.0f;
#pragma unroll
            for (int j = 0; j < 8; j++) d0 += qr[i][j] * kx[j];
            dot[i] = d0;
        }
#pragma unroll
        for (int off = 16; off; off >>= 1)
#pragma unroll
            for (int i = 0; i < 8; i++)
                dot[i] += __shfl_xor_sync(0xffffffffu, dot[i], off);

        float m = dot[0];
#pragma unroll
        for (int i = 1; i < 8; i++) m = fmaxf(m, dot[i]);
        float e[8]; float ssum = 0.0f;
#pragma unroll
        for (int i = 0; i < 8; i++) { e[i] = __expf(dot[i] - m); ssum += e[i]; }
        float inv = 1.0f / ssum;

        float vx[8];
        { float2 f;
          f = bf2f(vu.x); vx[0] = f.x; vx[1] = f.y;
          f = bf2f(vu.y); vx[2] = f.x; vx[3] = f.y;
          f = bf2f(vu.z); vx[4] = f.x; vx[5] = f.y;
          f = bf2f(vu.w); vx[6] = f.x; vx[7] = f.y; }
#pragma unroll
        for (int i = 0; i < 8; i++) {
            float a = e[i] * inv + 1e-8f;
            den[i] += a;
#pragma unroll
            for (int j = 0; j < 8; j++) acc[i][j] += a * vx[j];
        }

        n = nn; ku = nku; vu = nvu;
    }

    // in-CTA reduce across 8 warps
    float* sA = sred;
    float* sD = sred + 8 * 2048;
#pragma unroll
    for (int i = 0; i < 8; i++) {
        *(float4*)(sA + wid * 2048 + i * 256 + lane * 8)     =
            make_float4(acc[i][0], acc[i][1], acc[i][2], acc[i][3]);
        *(float4*)(sA + wid * 2048 + i * 256 + lane * 8 + 4) =
            make_float4(acc[i][4], acc[i][5], acc[i][6], acc[i][7]);
    }
    if (lane == 0) {
#pragma unroll
        for (int i = 0; i < 8; i++) sD[wid * 8 + i] = den[i];
    }
    __syncthreads();

    float* pn = pnum + ((size_t)b * PRED + blockIdx.x) * S * D;
#pragma unroll
    for (int r = 0; r < 8; r++) {
        int idx = tid + r * 256;
        float s = 0.0f;
#pragma unroll
        for (int w = 0; w < 8; w++) s += sA[w * 2048 + idx];
        pn[idx] = s;
    }
    if (tid < 8) {
        float s = 0.0f;
#pragma unroll
        for (int w = 0; w < 8; w++) s += sD[w * 8 + tid];
        pden[(b * PRED + blockIdx.x) * S + tid] = s;
    }
}

__global__ void attn_reduce_kernel(const float* __restrict__ pnum,
                                   const float* __restrict__ pden,
                                   float* __restrict__ upd)
{
    int idx = blockIdx.x * blockDim.x + threadIdx.x;  // over 64*2048
    int b = idx >> 11;
    int i = (idx >> 8) & 7;
    float s = 0.0f, d = 0.0f;
#pragma unroll
    for (int w = 0; w < PRED; w++) {
        s += pnum[((size_t)b * PRED + w) * S * D + (idx & 2047)];
        d += pden[(b * PRED + w) * S + i];
    }
    upd[idx] = s / d;
}

// ---------------- slot_gru: GRU gate GEMMs + pointwise -----------------------
// grid (4, BATCH): chunk c covers d in [c*64, c*64+64); 256 threads.
// thread t: d = c*64 + (t&63), slot pair sg = t>>6 -> slots 2*sg, 2*sg+1
__global__ void __launch_bounds__(256) slot_gru_kernel(
    const float* __restrict__ upd_g, const float* __restrict__ slots,
    const float* __restrict__ w_ih, const float* __restrict__ b_ih,
    const float* __restrict__ w_hh, const float* __restrict__ b_hh,
    float* __restrict__ slots2)
{
    __shared__ float su[S][D];
    __shared__ float sp[S][D];
    const int b   = blockIdx.y;
    const int c   = blockIdx.x;
    const int tid = threadIdx.x;

#pragma unroll
    for (int r = 0; r < 8; r++) {
        int idx = tid + r * 256;
        su[idx >> 8][idx & 255] = upd_g[(size_t)b * S * D + idx];
        sp[idx >> 8][idx & 255] = slots[(size_t)b * S * D + idx];
    }
    __syncthreads();

    const int dl = tid & 63;
    const int d  = c * 64 + dl;
    const int i0 = (tid >> 6) * 2;

    float ax[3][2], ah[3][2];
#pragma unroll
    for (int g = 0; g < 3; g++) {
        const float* wi = w_ih + (size_t)(g * D + d) * D;
        const float* wh = w_hh + (size_t)(g * D + d) * D;
        float a0 = 0.f, a1 = 0.f, h0 = 0.f, h1 = 0.f;
#pragma unroll 4
        for (int k = 0; k < D; k += 4) {
            float4 wiv = *(const float4*)(wi + k);
            float4 whv = *(const float4*)(wh + k);
            float4 u0 = *(const float4*)&su[i0][k];
            float4 u1 = *(const float4*)&su[i0 + 1][k];
            float4 p0 = *(const float4*)&sp[i0][k];
            float4 p1 = *(const float4*)&sp[i0 + 1][k];
            a0 += wiv.x * u0.x + wiv.y * u0.y + wiv.z * u0.z + wiv.w * u0.w;
            a1 += wiv.x * u1.x + wiv.y * u1.y + wiv.z * u1.z + wiv.w * u1.w;
            h0 += whv.x * p0.x + whv.y * p0.y + whv.z * p0.z + whv.w * p0.w;
            h1 += whv.x * p1.x + whv.y * p1.y + whv.z * p1.z + whv.w * p1.w;
        }
        float bi = b_ih[g * D + d], bh = b_hh[g * D + d];
        ax[g][0] = a0 + bi; ax[g][1] = a1 + bi;
        ah[g][0] = h0 + bh; ah[g][1] = h1 + bh;
    }

#pragma unroll
    for (int s = 0; s < 2; s++) {
        int i = i0 + s;
        float r = 1.0f / (1.0f + expf(-(ax[0][s] + ah[0][s])));
        float z = 1.0f / (1.0f + expf(-(ax[1][s] + ah[1][s])));
        float nv = tanhf(ax[2][s] + r * ah[2][s]);
        float prev = sp[i][d];
        slots2[(size_t)b * S * D + i * D + d] = (1.0f - z) * nv + z * prev;
    }
}

// ---------------- slot_mlp: LN + relu-MLP + residual -------------------------
// grid (2, BATCH): half h covers out cols [h*128, h*128+128); 256 threads.
__global__ void __launch_bounds__(256) slot_mlp_kernel(
    const float* __restrict__ slots2,
    const float* __restrict__ w1, const float* __restrict__ b1,
    const float* __restrict__ w2, const float* __restrict__ b2,
    const float* __restrict__ gff, const float* __restrict__ bff,
    float* __restrict__ slots_out)
{
    __shared__ float sn[S][D];
    __shared__ float sh[S][D];
    const int b    = blockIdx.y;
    const int half = blockIdx.x;
    const int tid  = threadIdx.x;
    const int wid  = tid >> 5;
    const int lane = tid & 31;

    {   // LN row wid
        const float* row = slots2 + ((size_t)b * S + wid) * D;
        float4 a = *(const float4*)(row + lane * 4);
        float4 c = *(const float4*)(row + 128 + lane * 4);
        float s  = a.x + a.y + a.z + a.w + c.x + c.y + c.z + c.w;
        float s2 = a.x*a.x + a.y*a.y + a.z*a.z + a.w*a.w
                 + c.x*c.x + c.y*c.y + c.z*c.z + c.w*c.w;
#pragma unroll
        for (int off = 16; off; off >>= 1) {
            s  += __shfl_xor_sync(0xffffffffu, s,  off);
            s2 += __shfl_xor_sync(0xffffffffu, s2, off);
        }
        float mean = s * (1.0f / 256.0f);
        float rstd = rsqrtf(s2 * (1.0f / 256.0f) - mean * mean + 1e-5f);
        float4 g0 = *(const float4*)(gff + lane * 4);
        float4 g1 = *(const float4*)(gff + 128 + lane * 4);
        float4 e0 = *(const float4*)(bff + lane * 4);
        float4 e1 = *(const float4*)(bff + 128 + lane * 4);
        sn[wid][lane * 4 + 0] = (a.x - mean) * rstd * g0.x + e0.x;
        sn[wid][lane * 4 + 1] = (a.y - mean) * rstd * g0.y + e0.y;
        sn[wid][lane * 4 + 2] = (a.z - mean) * rstd * g0.z + e0.z;
        sn[wid][lane * 4 + 3] = (a.w - mean) * rstd * g0.w + e0.w;
        sn[wid][128 + lane * 4 + 0] = (c.x - mean) * rstd * g1.x + e1.x;
        sn[wid][128 + lane * 4 + 1] = (c.y - mean) * rstd * g1.y + e1.y;
        sn[wid][128 + lane * 4 + 2] = (c.z - mean) * rstd * g1.z + e1.z;
        sn[wid][128 + lane * 4 + 3] = (c.w - mean) * rstd * g1.w + e1.w;
    }
    __syncthreads();

    // h[i][tid] = relu(sn[i] . w1[tid] + b1[tid])
    {
        float acc[S];
#pragma unroll
        for (int i = 0; i < S; i++) acc[i] = 0.0f;
        const float* wrow = w1 + (size_t)tid * D;
#pragma unroll 4
        for (int k = 0; k < D; k += 4) {
            float4 w4 = *(const float4*)(wrow + k);
#pragma unroll
            for (int i = 0; i < S; i++) {
                float4 s4 = *(const float4*)&sn[i][k];
                acc[i] += s4.x * w4.x + s4.y * w4.y + s4.z * w4.z + s4.w * w4.w;
            }
        }
        float bb = b1[tid];
#pragma unroll
        for (int i = 0; i < S; i++) sh[i][tid] = fmaxf(acc[i] + bb, 0.0f);
    }
    __syncthreads();

    // out[i][col] = slots2[i][col] + sh[i] . w2[col] + b2[col]
    {
        const int col = half * 128 + (tid & 127);
        const int ib  = (tid >> 7) * 4;       // 4 slots per thread
        float acc[4] = {0, 0, 0, 0};
        const float* wrow = w2 + (size_t)col * D;
#pragma unroll 4
        for (int k = 0; k < D; k += 4) {
            float4 w4 = *(const float4*)(wrow + k);
#pragma unroll
            for (int s = 0; s < 4; s++) {
                float4 h4 = *(const float4*)&sh[ib + s][k];
                acc[s] += h4.x * w4.x + h4.y * w4.y + h4.z * w4.z + h4.w * w4.w;
            }
        }
        float bb = b2[col];
#pragma unroll
        for (int s = 0; s < 4; s++) {
            int i = ib + s;
            slots_out[(size_t)b * S * D + i * D + col] =
                slots2[(size_t)b * S * D + i * D + col] + acc[s] + bb;
        }
    }
}

// ---------------- host orchestration ----------------------------------------
extern "C" void kernel_launch(void* const* d_in, const int* in_sizes, int n_in,
                              void* d_out, int out_size)
{
    const float* inputs     = (const float*)d_in[0];
    const float* init_slots = (const float*)d_in[1];
    const float* wq   = (const float*)d_in[2];  const float* bq   = (const float*)d_in[3];
    const float* wk   = (const float*)d_in[4];  const float* bk   = (const float*)d_in[5];
    const float* wv   = (const float*)d_in[6];  const float* bv   = (const float*)d_in[7];
    const float* w_ih = (const float*)d_in[8];  const float* b_ih = (const float*)d_in[9];
    const float* w_hh = (const float*)d_in[10]; const float* b_hh = (const float*)d_in[11];
    const float* w1   = (const float*)d_in[12]; const float* b1   = (const float*)d_in[13];
    const float* w2   = (const float*)d_in[14]; const float* b2   = (const float*)d_in[15];
    const float* gin  = (const float*)d_in[16]; const float* bin  = (const float*)d_in[17];
    const float* gsl  = (const float*)d_in[18]; const float* bsl  = (const float*)d_in[19];
    const float* gff  = (const float*)d_in[20]; const float* bff  = (const float*)d_in[21];

    __nv_bfloat16 *xln16, *k16, *v16, *w16;
    float *bias, *slots, *slots2, *qb, *upd, *pnum, *pden;
    cudaGetSymbolAddress((void**)&xln16,  g_xln16);
    cudaGetSymbolAddress((void**)&k16,    g_k16);
    cudaGetSymbolAddress((void**)&v16,    g_v16);
    cudaGetSymbolAddress((void**)&w16,    g_w16);
    cudaGetSymbolAddress((void**)&bias,   g_bias);
    cudaGetSymbolAddress((void**)&slots,  g_slots);
    cudaGetSymbolAddress((void**)&slots2, g_slots2);
    cudaGetSymbolAddress((void**)&qb,     g_qbuf);
    cudaGetSymbolAddress((void**)&upd,    g_upd);
    cudaGetSymbolAddress((void**)&pnum,   g_pnum);
    cudaGetSymbolAddress((void**)&pden,   g_pden);

    cudaFuncSetAttribute(kv_mma_kernel, cudaFuncAttributeMaxDynamicSharedMemorySize, KV_SMEM);
    const int ATTN_SMEM = (8 * 2048 + 64) * sizeof(float);
    cudaFuncSetAttribute(attn_pass_kernel, cudaFuncAttributeMaxDynamicSharedMemorySize, ATTN_SMEM);

    // prologue
    cudaMemcpyAsync(slots, init_slots, (size_t)ROWS_SLOT * D * sizeof(float),
                    cudaMemcpyDeviceToDevice);
    conv_w_kernel<<<D * D / 256, 256>>>(wk, wv, bk, bv, w16, bias);
    ln_rows_bf16_kernel<<<ROWS_BIG / 8, 256>>>(inputs, xln16, gin, bin);
    kv_mma_kernel<<<dim3(4, ROWS_BIG / BMT), 256, KV_SMEM>>>(xln16, w16, bias, k16, v16);

    for (int it = 0; it < 3; it++) {
        slot_pre_kernel<<<BATCH, 256>>>(slots, wq, bq, gsl, bsl, qb);
        attn_pass_kernel<<<dim3(PRED, BATCH), 256, ATTN_SMEM>>>(qb, k16, v16, pnum, pden);
        attn_reduce_kernel<<<(BATCH * S * D) / 256, 256>>>(pnum, pden, upd);
        slot_gru_kernel<<<dim3(4, BATCH), 256>>>(upd, slots, w_ih, b_ih, w_hh, b_hh, slots2);
        slot_mlp_kernel<<<dim3(2, BATCH), 256>>>(slots2, w1, b1, w2, b2, gff, bff, slots);
    }

    cudaMemcpyAsync(d_out, slots, (size_t)ROWS_SLOT * D * sizeof(float),
                    cudaMemcpyDeviceToDevice);
}

// round 7
// speedup vs baseline: 1.1654x; 1.1654x over previous
#include <cuda_runtime.h>
#include <cuda_bf16.h>
#include <math.h>
#include <stdint.h>

#define D 256
#define BATCH 64
#define NTOK 4096
#define S 8
#define ROWS_BIG (BATCH * NTOK)   // 262144
#define ROWS_SLOT (BATCH * S)     // 512
#define PRED 8                    // partials per batch after in-CTA reduce

// ---------------- scratch (device globals; no allocations allowed) ----------
__device__ __nv_bfloat16 g_xln16[(size_t)ROWS_BIG * D];   // 134 MB
__device__ __nv_bfloat16 g_k16[(size_t)ROWS_BIG * D];     // 134 MB
__device__ __nv_bfloat16 g_v16[(size_t)ROWS_BIG * D];     // 134 MB
__device__ __nv_bfloat16 g_w16[2 * D * D];                // concat(Wk, Wv) [512,256]
__device__ float g_bias[2 * D];                           // concat(bk, bv)
__device__ float g_slots[ROWS_SLOT * D];
__device__ float g_sn[ROWS_SLOT * D];
__device__ float g_qbuf[ROWS_SLOT * D];
__device__ float g_upd[ROWS_SLOT * D];
__device__ float g_hbuf[ROWS_SLOT * D];
__device__ float g_gx[ROWS_SLOT * 3 * D];
__device__ float g_gh[ROWS_SLOT * 3 * D];
__device__ float g_pnum[(size_t)BATCH * PRED * S * D];    // 4.2 MB
__device__ float g_pden[BATCH * PRED * S];

// ---------------- PTX helpers (arch-agnostic: sm_80+ features only) ----------
__device__ __forceinline__ uint32_t smem_u32(const void* p) {
    uint32_t a;
    asm("{ .reg .u64 t; cvta.to.shared.u64 t, %1; cvt.u32.u64 %0, t; }" : "=r"(a) : "l"(p));
    return a;
}
__device__ __forceinline__ void cpasync16(uint32_t saddr, const void* g) {
    asm volatile("cp.async.cg.shared.global [%0], [%1], 16;" :: "r"(saddr), "l"(g));
}
#define CP_COMMIT() asm volatile("cp.async.commit_group;" ::: "memory")
#define CP_WAIT(n)  asm volatile("cp.async.wait_group %0;" :: "n"(n) : "memory")

__device__ __forceinline__ void ldsm_x4(uint32_t& r0, uint32_t& r1, uint32_t& r2, uint32_t& r3,
                                        uint32_t addr) {
    asm volatile("ldmatrix.sync.aligned.m8n8.x4.shared.b16 {%0,%1,%2,%3}, [%4];"
                 : "=r"(r0), "=r"(r1), "=r"(r2), "=r"(r3) : "r"(addr));
}
__device__ __forceinline__ void mma16816(float* d, const uint32_t* a, const uint32_t* b) {
    asm volatile("mma.sync.aligned.m16n8k16.row.col.f32.bf16.bf16.f32 "
                 "{%0,%1,%2,%3}, {%4,%5,%6,%7}, {%8,%9}, {%0,%1,%2,%3};"
                 : "+f"(d[0]), "+f"(d[1]), "+f"(d[2]), "+f"(d[3])
                 : "r"(a[0]), "r"(a[1]), "r"(a[2]), "r"(a[3]), "r"(b[0]), "r"(b[1]));
}
__device__ __forceinline__ float2 bf2f(uint32_t u) {
    __nv_bfloat162 h = *reinterpret_cast<__nv_bfloat162*>(&u);
    return __bfloat1622float2(h);
}

// ---------------- weights fp32 -> bf16 (concat layout) -----------------------
__global__ void conv_w_kernel(const float* __restrict__ wk, const float* __restrict__ wv,
                              const float* __restrict__ bk, const float* __restrict__ bv,
                              __nv_bfloat16* __restrict__ w16, float* __restrict__ bias)
{
    int i = blockIdx.x * 256 + threadIdx.x;   // 0..65535
    w16[i]             = __float2bfloat16(wk[i]);
    w16[i + D * D]     = __float2bfloat16(wv[i]);
    if (i < D) { bias[i] = bk[i]; bias[i + D] = bv[i]; }
}

// ---------------- LayerNorm fp32 -> fp32 (slot rows) -------------------------
__global__ void ln_rows_kernel(const float* __restrict__ in, float* __restrict__ out,
                               const float* __restrict__ gamma, const float* __restrict__ beta,
                               int nrows)
{
    int gw   = (blockIdx.x * blockDim.x + threadIdx.x) >> 5;
    int lane = threadIdx.x & 31;
    if (gw >= nrows) return;
    const float* row = in + (size_t)gw * D;
    float4 a = *(const float4*)(row + lane * 4);
    float4 b = *(const float4*)(row + 128 + lane * 4);
    float s  = a.x + a.y + a.z + a.w + b.x + b.y + b.z + b.w;
    float s2 = a.x*a.x + a.y*a.y + a.z*a.z + a.w*a.w
             + b.x*b.x + b.y*b.y + b.z*b.z + b.w*b.w;
#pragma unroll
    for (int off = 16; off; off >>= 1) {
        s  += __shfl_xor_sync(0xffffffffu, s,  off);
        s2 += __shfl_xor_sync(0xffffffffu, s2, off);
    }
    float mean = s * (1.0f / 256.0f);
    float var  = s2 * (1.0f / 256.0f) - mean * mean;
    float rstd = rsqrtf(var + 1e-5f);
    float4 g0 = *(const float4*)(gamma + lane * 4);
    float4 g1 = *(const float4*)(gamma + 128 + lane * 4);
    float4 e0 = *(const float4*)(beta + lane * 4);
    float4 e1 = *(const float4*)(beta + 128 + lane * 4);
    float4 o0, o1;
    o0.x = (a.x - mean) * rstd * g0.x + e0.x;
    o0.y = (a.y - mean) * rstd * g0.y + e0.y;
    o0.z = (a.z - mean) * rstd * g0.z + e0.z;
    o0.w = (a.w - mean) * rstd * g0.w + e0.w;
    o1.x = (b.x - mean) * rstd * g1.x + e1.x;
    o1.y = (b.y - mean) * rstd * g1.y + e1.y;
    o1.z = (b.z - mean) * rstd * g1.z + e1.z;
    o1.w = (b.w - mean) * rstd * g1.w + e1.w;
    *(float4*)(out + (size_t)gw * D + lane * 4)       = o0;
    *(float4*)(out + (size_t)gw * D + 128 + lane * 4) = o1;
}

// ---------------- LayerNorm fp32 -> bf16 (big input) -------------------------
__global__ void ln_rows_bf16_kernel(const float* __restrict__ in, __nv_bfloat16* __restrict__ out,
                                    const float* __restrict__ gamma, const float* __restrict__ beta)
{
    int gw   = (blockIdx.x * blockDim.x + threadIdx.x) >> 5;
    int lane = threadIdx.x & 31;
    const float* row = in + (size_t)gw * D;
    float4 a = *(const float4*)(row + lane * 4);
    float4 b = *(const float4*)(row + 128 + lane * 4);
    float s  = a.x + a.y + a.z + a.w + b.x + b.y + b.z + b.w;
    float s2 = a.x*a.x + a.y*a.y + a.z*a.z + a.w*a.w
             + b.x*b.x + b.y*b.y + b.z*b.z + b.w*b.w;
#pragma unroll
    for (int off = 16; off; off >>= 1) {
        s  += __shfl_xor_sync(0xffffffffu, s,  off);
        s2 += __shfl_xor_sync(0xffffffffu, s2, off);
    }
    float mean = s * (1.0f / 256.0f);
    float var  = s2 * (1.0f / 256.0f) - mean * mean;
    float rstd = rsqrtf(var + 1e-5f);
    float4 g0 = *(const float4*)(gamma + lane * 4);
    float4 g1 = *(const float4*)(gamma + 128 + lane * 4);
    float4 e0 = *(const float4*)(beta + lane * 4);
    float4 e1 = *(const float4*)(beta + 128 + lane * 4);
    __nv_bfloat162 p[4];
    p[0] = __float22bfloat162_rn(make_float2((a.x - mean) * rstd * g0.x + e0.x,
                                             (a.y - mean) * rstd * g0.y + e0.y));
    p[1] = __float22bfloat162_rn(make_float2((a.z - mean) * rstd * g0.z + e0.z,
                                             (a.w - mean) * rstd * g0.w + e0.w));
    p[2] = __float22bfloat162_rn(make_float2((b.x - mean) * rstd * g1.x + e1.x,
                                             (b.y - mean) * rstd * g1.y + e1.y));
    p[3] = __float22bfloat162_rn(make_float2((b.z - mean) * rstd * g1.z + e1.z,
                                             (b.w - mean) * rstd * g1.w + e1.w));
    __nv_bfloat16* o = out + (size_t)gw * D;
    *(uint2*)(o + lane * 4)       = make_uint2(*(uint32_t*)&p[0], *(uint32_t*)&p[1]);
    *(uint2*)(o + 128 + lane * 4) = make_uint2(*(uint32_t*)&p[2], *(uint32_t*)&p[3]);
}

// ---------------- KV projection: bf16 mma.sync GEMM --------------------------
// C[262144, 512] = A[262144,256] @ W[512,256]^T ; cols 0-255 -> K, 256-511 -> V
// CTA 128x128. All 4 k-block stages (A+W tiles, 128 KB total) are preloaded via
// cp.async in 4 commit groups; compute streams through with progressive
// wait_group 3/2/1/0, so memory latency overlaps all compute. No min-blocks
// register cap (round-6 lesson: capping to 128 regs spills the mainloop).
#define BMT 128
#define BNT 128
#define KV_STAGE 32768                 // per k-block: A 16KB + B 16KB
#define KV_SMEM  (4 * KV_STAGE)        // 128 KB

__global__ void __launch_bounds__(256) kv_mma_kernel(
    const __nv_bfloat16* __restrict__ A,
    const __nv_bfloat16* __restrict__ W,
    const float* __restrict__ bias,
    __nv_bfloat16* __restrict__ Kout,
    __nv_bfloat16* __restrict__ Vout)
{
    extern __shared__ char smem[];
    const int tid  = threadIdx.x;
    const int lane = tid & 31;
    const int wid  = tid >> 5;
    const int wm   = wid >> 1;
    const int wn   = wid & 1;
    const int bm   = blockIdx.y * BMT;
    const int bn   = blockIdx.x * BNT;
    const uint32_t sb = smem_u32(smem);

    const char* Ag = (const char*)A + (size_t)bm * 512;
    const char* Wg = (const char*)W + (size_t)bn * 512;

    float acc[2][8][4];
#pragma unroll
    for (int mi = 0; mi < 2; mi++)
#pragma unroll
        for (int nj = 0; nj < 8; nj++)
#pragma unroll
            for (int x = 0; x < 4; x++) acc[mi][nj][x] = 0.0f;

#define LOAD_STAGE(kb) do {                                                   \
        uint32_t abase = sb + (kb) * KV_STAGE;                                \
        uint32_t bbase = abase + 16384;                                       \
        const char* ag = Ag + (kb) * 128;                                     \
        const char* wg = Wg + (kb) * 128;                                     \
        _Pragma("unroll")                                                     \
        for (int i = 0; i < 4; i++) {                                         \
            int ci = tid + i * 256;                                           \
            int r = ci >> 3, c = ci & 7;                                      \
            cpasync16(abase + r * 128 + ((c ^ (r & 7)) * 16),                 \
                      ag + (size_t)r * 512 + c * 16);                         \
        }                                                                     \
        _Pragma("unroll")                                                     \
        for (int i = 0; i < 4; i++) {                                         \
            int ci = tid + i * 256;                                           \
            int r = ci >> 3, c = ci & 7;                                      \
            cpasync16(bbase + r * 128 + ((c ^ (r & 7)) * 16),                 \
                      wg + (size_t)r * 512 + c * 16);                         \
        }                                                                     \
        CP_COMMIT();                                                          \
    } while (0)

    LOAD_STAGE(0);
    LOAD_STAGE(1);
    LOAD_STAGE(2);
    LOAD_STAGE(3);

#pragma unroll
    for (int kb = 0; kb < 4; kb++) {
        if      (kb == 0) CP_WAIT(3);
        else if (kb == 1) CP_WAIT(2);
        else if (kb == 2) CP_WAIT(1);
        else              CP_WAIT(0);
        __syncthreads();

        uint32_t abase = sb + kb * KV_STAGE;
        uint32_t bbase = abase + 16384;
#pragma unroll
        for (int ks = 0; ks < 4; ks++) {
            uint32_t afr[2][4];
#pragma unroll
            for (int mi = 0; mi < 2; mi++) {
                int row   = wm * 32 + mi * 16 + (lane & 15);
                int chunk = (ks * 2 + (lane >> 4)) ^ (row & 7);
                ldsm_x4(afr[mi][0], afr[mi][1], afr[mi][2], afr[mi][3],
                        abase + row * 128 + chunk * 16);
            }
            uint32_t bfr[8][2];
#pragma unroll
            for (int njp = 0; njp < 4; njp++) {
                int row   = wn * 64 + njp * 16 + ((lane >> 4) & 1) * 8 + (lane & 7);
                int chunk = (ks * 2 + ((lane >> 3) & 1)) ^ (row & 7);
                uint32_t r0, r1, r2, r3;
                ldsm_x4(r0, r1, r2, r3, bbase + row * 128 + chunk * 16);
                bfr[njp * 2][0]     = r0; bfr[njp * 2][1]     = r1;
                bfr[njp * 2 + 1][0] = r2; bfr[njp * 2 + 1][1] = r3;
            }
#pragma unroll
            for (int mi = 0; mi < 2; mi++)
#pragma unroll
                for (int nj = 0; nj < 8; nj++)
                    mma16816(acc[mi][nj], afr[mi], bfr[nj]);
        }
    }

    __nv_bfloat16* outp;
    int cb;
    if (bn < 256) { outp = Kout; cb = bn; } else { outp = Vout; cb = bn - 256; }
#pragma unroll
    for (int mi = 0; mi < 2; mi++) {
        int r0 = bm + wm * 32 + mi * 16 + (lane >> 2);
#pragma unroll
        for (int nj = 0; nj < 8; nj++) {
            int ncol = wn * 64 + nj * 8 + (lane & 3) * 2;
            float2 bs = *(const float2*)&bias[bn + ncol];
            __nv_bfloat162 lo = __float22bfloat162_rn(
                make_float2(acc[mi][nj][0] + bs.x, acc[mi][nj][1] + bs.y));
            __nv_bfloat162 hi = __float22bfloat162_rn(
                make_float2(acc[mi][nj][2] + bs.x, acc[mi][nj][3] + bs.y));
            *(__nv_bfloat162*)(outp + (size_t)r0 * D + cb + ncol)       = lo;
            *(__nv_bfloat162*)(outp + (size_t)(r0 + 8) * D + cb + ncol) = hi;
        }
    }
#undef LOAD_STAGE
}

// ---------------- Small fp32 SGEMM: C[M,N] = A[M,K] @ W[N,K]^T + bias --------
template <int BM, int BN, int BK, int TM, int TN>
__global__ void sgemm_kernel(const float* __restrict__ A, const float* __restrict__ W,
                             const float* __restrict__ bias, float* __restrict__ C,
                             int M, int N, int K, int relu, int accum)
{
    constexpr int THREADS = (BM / TM) * (BN / TN);
    __shared__ float As[BK][BM + 4];
    __shared__ float Ws[BK][BN + 4];
    const int tid  = threadIdx.x;
    const int bm   = blockIdx.y * BM;
    const int bn   = blockIdx.x * BN;
    const int tcol = (tid % (BN / TN)) * TN;
    const int trow = (tid / (BN / TN)) * TM;

    float acc[TM][TN];
#pragma unroll
    for (int i = 0; i < TM; i++)
#pragma unroll
        for (int j = 0; j < TN; j++) acc[i][j] = 0.0f;

    for (int k0 = 0; k0 < K; k0 += BK) {
        constexpr int AL = (BM * BK) / (THREADS * 4);
#pragma unroll
        for (int t = 0; t < AL; t++) {
            int idx = (tid + t * THREADS) * 4;
            int r = idx / BK, c = idx % BK;
            float4 val = *(const float4*)&A[(size_t)(bm + r) * K + k0 + c];
            As[c + 0][r] = val.x; As[c + 1][r] = val.y;
            As[c + 2][r] = val.z; As[c + 3][r] = val.w;
        }
        constexpr int WL = (BN * BK) / (THREADS * 4);
#pragma unroll
        for (int t = 0; t < WL; t++) {
            int idx = (tid + t * THREADS) * 4;
            int r = idx / BK, c = idx % BK;
            float4 val = *(const float4*)&W[(size_t)(bn + r) * K + k0 + c];
            Ws[c + 0][r] = val.x; Ws[c + 1][r] = val.y;
            Ws[c + 2][r] = val.z; Ws[c + 3][r] = val.w;
        }
        __syncthreads();
#pragma unroll
        for (int kk = 0; kk < BK; kk++) {
            float a[TM], b[TN];
#pragma unroll
            for (int i = 0; i < TM; i += 4) {
                float4 t4 = *(const float4*)&As[kk][trow + i];
                a[i] = t4.x; a[i + 1] = t4.y; a[i + 2] = t4.z; a[i + 3] = t4.w;
            }
#pragma unroll
            for (int j = 0; j < TN; j += 4) {
                float4 t4 = *(const float4*)&Ws[kk][tcol + j];
                b[j] = t4.x; b[j + 1] = t4.y; b[j + 2] = t4.z; b[j + 3] = t4.w;
            }
#pragma unroll
            for (int i = 0; i < TM; i++)
#pragma unroll
                for (int j = 0; j < TN; j++) acc[i][j] += a[i] * b[j];
        }
        __syncthreads();
    }

#pragma unroll
    for (int i = 0; i < TM; i++) {
        int r = bm + trow + i;
#pragma unroll
        for (int j = 0; j < TN; j += 4) {
            int c = bn + tcol + j;
            float4 o;
            o.x = acc[i][j + 0] + bias[c + 0];
            o.y = acc[i][j + 1] + bias[c + 1];
            o.z = acc[i][j + 2] + bias[c + 2];
            o.w = acc[i][j + 3] + bias[c + 3];
            if (relu) {
                o.x = fmaxf(o.x, 0.0f); o.y = fmaxf(o.y, 0.0f);
                o.z = fmaxf(o.z, 0.0f); o.w = fmaxf(o.w, 0.0f);
            }
            if (accum) {
                float4 old = *(const float4*)&C[(size_t)r * N + c];
                o.x += old.x; o.y += old.y; o.z += old.z; o.w += old.w;
            }
            *(float4*)&C[(size_t)r * N + c] = o;
        }
    }
}

// ---------------- Fused attention pass (bf16 k/v, in-CTA reduce) -------------
__global__ void __launch_bounds__(256) attn_pass_kernel(
    const float* __restrict__ q,
    const __nv_bfloat16* __restrict__ k,
    const __nv_bfloat16* __restrict__ v,
    float* __restrict__ pnum,
    float* __restrict__ pden)
{
    extern __shared__ float sred[];          // 8*2048 floats + 64 den
    const int b    = blockIdx.y;
    const int wid  = threadIdx.x >> 5;
    const int lane = threadIdx.x & 31;
    const int tid  = threadIdx.x;
    const int wg   = blockIdx.x * 8 + wid;   // 0..63
    const float scale = 0.0625f;

    float qr[8][8];
    const float* qb = q + b * S * D;
#pragma unroll
    for (int i = 0; i < 8; i++) {
        float4 q0 = *(const float4*)(qb + i * D + lane * 8);
        float4 q1 = *(const float4*)(qb + i * D + lane * 8 + 4);
        qr[i][0] = q0.x * scale; qr[i][1] = q0.y * scale;
        qr[i][2] = q0.z * scale; qr[i][3] = q0.w * scale;
        qr[i][4] = q1.x * scale; qr[i][5] = q1.y * scale;
        qr[i][6] = q1.z * scale; qr[i][7] = q1.w * scale;
    }

    float acc[8][8];
#pragma unroll
    for (int i = 0; i < 8; i++)
#pragma unroll
        for (int j = 0; j < 8; j++) acc[i][j] = 0.0f;
    float den[8] = {0, 0, 0, 0, 0, 0, 0, 0};

    const size_t base = (size_t)b * NTOK * D;
    const __nv_bfloat16* kb = k + base;
    const __nv_bfloat16* vb = v + base;

    int n = wg;
    uint4 ku = *(const uint4*)(kb + (size_t)n * D + lane * 8);
    uint4 vu = *(const uint4*)(vb + (size_t)n * D + lane * 8);

#pragma unroll 1
    for (int t = 0; t < 64; t++) {
        uint4 nku = ku, nvu = vu;
        int nn = n + 64;
        if (t < 63) {
            nku = *(const uint4*)(kb + (size_t)nn * D + lane * 8);
            nvu = *(const uint4*)(vb + (size_t)nn * D + lane * 8);
        }

        float kx[8];
        { float2 f;
          f = bf2f(ku.x); kx[0] = f.x; kx[1] = f.y;
          f = bf2f(ku.y); kx[2] = f.x; kx[3] = f.y;
          f = bf2f(ku.z); kx[4] = f.x; kx[5] = f.y;
          f = bf2f(ku.w); kx[6] = f.x; kx[7] = f.y; }

        float dot[8];
#pragma unroll
        for (int i = 0; i < 8; i++) {
            float d0 = 0.0f;
#pragma unroll
            for (int j = 0; j < 8; j++) d0 += qr[i][j] * kx[j];
            dot[i] = d0;
        }
#pragma unroll
        for (int off = 16; off; off >>= 1)
#pragma unroll
            for (int i = 0; i < 8; i++)
                dot[i] += __shfl_xor_sync(0xffffffffu, dot[i], off);

        float m = dot[0];
#pragma unroll
        for (int i = 1; i < 8; i++) m = fmaxf(m, dot[i]);
        float e[8]; float ssum = 0.0f;
#pragma unroll
        for (int i = 0; i < 8; i++) { e[i] = __expf(dot[i] - m); ssum += e[i]; }
        float inv = 1.0f / ssum;

        float vx[8];
        { float2 f;
          f = bf2f(vu.x); vx[0] = f.x; vx[1] = f.y;
          f = bf2f(vu.y); vx[2] = f.x; vx[3] = f.y;
          f = bf2f(vu.z); vx[4] = f.x; vx[5] = f.y;
          f = bf2f(vu.w); vx[6] = f.x; vx[7] = f.y; }
#pragma unroll
        for (int i = 0; i < 8; i++) {
            float a = e[i] * inv + 1e-8f;
            den[i] += a;
#pragma unroll
            for (int j = 0; j < 8; j++) acc[i][j] += a * vx[j];
        }

        n = nn; ku = nku; vu = nvu;
    }

    // in-CTA reduce across 8 warps
    float* sA = sred;
    float* sD = sred + 8 * 2048;
#pragma unroll
    for (int i = 0; i < 8; i++) {
        *(float4*)(sA + wid * 2048 + i * 256 + lane * 8)     =
            make_float4(acc[i][0], acc[i][1], acc[i][2], acc[i][3]);
        *(float4*)(sA + wid * 2048 + i * 256 + lane * 8 + 4) =
            make_float4(acc[i][4], acc[i][5], acc[i][6], acc[i][7]);
    }
    if (lane == 0) {
#pragma unroll
        for (int i = 0; i < 8; i++) sD[wid * 8 + i] = den[i];
    }
    __syncthreads();

    float* pn = pnum + ((size_t)b * PRED + blockIdx.x) * S * D;
#pragma unroll
    for (int r = 0; r < 8; r++) {
        int idx = tid + r * 256;
        float s = 0.0f;
#pragma unroll
        for (int w = 0; w < 8; w++) s += sA[w * 2048 + idx];
        pn[idx] = s;
    }
    if (tid < 8) {
        float s = 0.0f;
#pragma unroll
        for (int w = 0; w < 8; w++) s += sD[w * 8 + tid];
        pden[(b * PRED + blockIdx.x) * S + tid] = s;
    }
}

__global__ void attn_reduce_kernel(const float* __restrict__ pnum,
                                   const float* __restrict__ pden,
                                   float* __restrict__ upd)
{
    int idx = blockIdx.x * blockDim.x + threadIdx.x;  // over 64*2048
    int b = idx >> 11;
    int i = (idx >> 8) & 7;
    float s = 0.0f, d = 0.0f;
#pragma unroll
    for (int w = 0; w < PRED; w++) {
        s += pnum[((size_t)b * PRED + w) * S * D + (idx & 2047)];
        d += pden[(b * PRED + w) * S + i];
    }
    upd[idx] = s / d;
}

// ---------------- GRU pointwise (torch gate order r,z,n) ---------------------
__global__ void gru_kernel(const float* __restrict__ gx, const float* __restrict__ gh,
                           float* __restrict__ slots)
{
    int idx = blockIdx.x * blockDim.x + threadIdx.x;  // over 512*256
    int row = idx >> 8, d = idx & 255;
    const float* gxr = gx + row * 3 * D;
    const float* ghr = gh + row * 3 * D;
    float xr = gxr[d], xz = gxr[D + d], xn = gxr[2 * D + d];
    float hr = ghr[d], hz = ghr[D + d], hn = ghr[2 * D + d];
    float r = 1.0f / (1.0f + expf(-(xr + hr)));
    float z = 1.0f / (1.0f + expf(-(xz + hz)));
    float nv = tanhf(xn + r * hn);
    float prev = slots[idx];
    slots[idx] = (1.0f - z) * nv + z * prev;
}

// ---------------- host orchestration ----------------------------------------
extern "C" void kernel_launch(void* const* d_in, const int* in_sizes, int n_in,
                              void* d_out, int out_size)
{
    const float* inputs     = (const float*)d_in[0];
    const float* init_slots = (const float*)d_in[1];
    const float* wq   = (const float*)d_in[2];  const float* bq   = (const float*)d_in[3];
    const float* wk   = (const float*)d_in[4];  const float* bk   = (const float*)d_in[5];
    const float* wv   = (const float*)d_in[6];  const float* bv   = (const float*)d_in[7];
    const float* w_ih = (const float*)d_in[8];  const float* b_ih = (const float*)d_in[9];
    const float* w_hh = (const float*)d_in[10]; const float* b_hh = (const float*)d_in[11];
    const float* w1   = (const float*)d_in[12]; const float* b1   = (const float*)d_in[13];
    const float* w2   = (const float*)d_in[14]; const float* b2   = (const float*)d_in[15];
    const float* gin  = (const float*)d_in[16]; const float* bin  = (const float*)d_in[17];
    const float* gsl  = (const float*)d_in[18]; const float* bsl  = (const float*)d_in[19];
    const float* gff  = (const float*)d_in[20]; const float* bff  = (const float*)d_in[21];

    __nv_bfloat16 *xln16, *k16, *v16, *w16;
    float *bias, *slots, *sn, *qb, *upd, *hb, *gx, *gh, *pnum, *pden;
    cudaGetSymbolAddress((void**)&xln16, g_xln16);
    cudaGetSymbolAddress((void**)&k16,   g_k16);
    cudaGetSymbolAddress((void**)&v16,   g_v16);
    cudaGetSymbolAddress((void**)&w16,   g_w16);
    cudaGetSymbolAddress((void**)&bias,  g_bias);
    cudaGetSymbolAddress((void**)&slots, g_slots);
    cudaGetSymbolAddress((void**)&sn,    g_sn);
    cudaGetSymbolAddress((void**)&qb,    g_qbuf);
    cudaGetSymbolAddress((void**)&upd,   g_upd);
    cudaGetSymbolAddress((void**)&hb,    g_hbuf);
    cudaGetSymbolAddress((void**)&gx,    g_gx);
    cudaGetSymbolAddress((void**)&gh,    g_gh);
    cudaGetSymbolAddress((void**)&pnum,  g_pnum);
    cudaGetSymbolAddress((void**)&pden,  g_pden);

    cudaFuncSetAttribute(kv_mma_kernel, cudaFuncAttributeMaxDynamicSharedMemorySize, KV_SMEM);
    const int ATTN_SMEM = (8 * 2048 + 64) * sizeof(float);
    cudaFuncSetAttribute(attn_pass_kernel, cudaFuncAttributeMaxDynamicSharedMemorySize, ATTN_SMEM);

    // prologue
    cudaMemcpyAsync(slots, init_slots, (size_t)ROWS_SLOT * D * sizeof(float),
                    cudaMemcpyDeviceToDevice);
    conv_w_kernel<<<D * D / 256, 256>>>(wk, wv, bk, bv, w16, bias);
    ln_rows_bf16_kernel<<<ROWS_BIG / 8, 256>>>(inputs, xln16, gin, bin);
    kv_mma_kernel<<<dim3(4, ROWS_BIG / BMT), 256, KV_SMEM>>>(xln16, w16, bias, k16, v16);

    for (int it = 0; it < 3; it++) {
        ln_rows_kernel<<<ROWS_SLOT / 8, 256>>>(slots, sn, gsl, bsl, ROWS_SLOT);
        sgemm_kernel<64, 64, 16, 4, 4><<<dim3(D / 64, ROWS_SLOT / 64), 256>>>(
            sn, wq, bq, qb, ROWS_SLOT, D, D, 0, 0);
        attn_pass_kernel<<<dim3(PRED, BATCH), 256, ATTN_SMEM>>>(qb, k16, v16, pnum, pden);
        attn_reduce_kernel<<<(BATCH * S * D) / 256, 256>>>(pnum, pden, upd);
        sgemm_kernel<64, 64, 16, 4, 4><<<dim3(3 * D / 64, ROWS_SLOT / 64), 256>>>(
            upd, w_ih, b_ih, gx, ROWS_SLOT, 3 * D, D, 0, 0);
        sgemm_kernel<64, 64, 16, 4, 4><<<dim3(3 * D / 64, ROWS_SLOT / 64), 256>>>(
            slots, w_hh, b_hh, gh, ROWS_SLOT, 3 * D, D, 0, 0);
        gru_kernel<<<(ROWS_SLOT * D) / 256, 256>>>(gx, gh, slots);
        ln_rows_kernel<<<ROWS_SLOT / 8, 256>>>(slots, sn, gff, bff, ROWS_SLOT);
        sgemm_kernel<64, 64, 16, 4, 4><<<dim3(D / 64, ROWS_SLOT / 64), 256>>>(
            sn, w1, b1, hb, ROWS_SLOT, D, D, 1, 0);
        sgemm_kernel<64, 64, 16, 4, 4><<<dim3(D / 64, ROWS_SLOT / 64), 256>>>(
            hb, w2, b2, slots, ROWS_SLOT, D, D, 0, 1);
    }

    cudaMemcpyAsync(d_out, slots, (size_t)ROWS_SLOT * D * sizeof(float),
                    cudaMemcpyDeviceToDevice);
}

// round 9
// speedup vs baseline: 1.2596x; 1.0808x over previous
#include <cuda_runtime.h>
#include <cuda_bf16.h>
#include <math.h>
#include <stdint.h>

#define D 256
#define BATCH 64
#define NTOK 4096
#define S 8
#define ROWS_BIG (BATCH * NTOK)   // 262144
#define ROWS_SLOT (BATCH * S)     // 512
#define PRED 8                    // partials per batch after in-CTA reduce

// ---------------- scratch (device globals; no allocations allowed) ----------
__device__ __nv_bfloat16 g_xln16[(size_t)ROWS_BIG * D];   // 134 MB
__device__ __nv_bfloat16 g_k16[(size_t)ROWS_BIG * D];     // 134 MB
__device__ __nv_bfloat16 g_v16[(size_t)ROWS_BIG * D];     // 134 MB
__device__ __nv_bfloat16 g_w16[2 * D * D];                // concat(Wk, Wv) [512,256]
__device__ float g_bias[2 * D];                           // concat(bk, bv)
__device__ float g_slots[ROWS_SLOT * D];
__device__ float g_qbuf[ROWS_SLOT * D];
__device__ float g_upd[ROWS_SLOT * D];
__device__ float g_hbuf[ROWS_SLOT * D];
__device__ float g_gx[ROWS_SLOT * 3 * D];
__device__ float g_gh[ROWS_SLOT * 3 * D];
__device__ float g_pnum[(size_t)BATCH * PRED * S * D];    // 4.2 MB
__device__ float g_pden[BATCH * PRED * S];

// ---------------- PTX helpers (arch-agnostic features only) ------------------
__device__ __forceinline__ uint32_t smem_u32(const void* p) {
    uint32_t a;
    asm("{ .reg .u64 t; cvta.to.shared.u64 t, %1; cvt.u32.u64 %0, t; }" : "=r"(a) : "l"(p));
    return a;
}
__device__ __forceinline__ void cpasync16(uint32_t saddr, const void* g) {
    asm volatile("cp.async.cg.shared.global [%0], [%1], 16;" :: "r"(saddr), "l"(g));
}
#define CP_COMMIT() asm volatile("cp.async.commit_group;" ::: "memory")
#define CP_WAIT(n)  asm volatile("cp.async.wait_group %0;" :: "n"(n) : "memory")

__device__ __forceinline__ void ldsm_x4(uint32_t& r0, uint32_t& r1, uint32_t& r2, uint32_t& r3,
                                        uint32_t addr) {
    asm volatile("ldmatrix.sync.aligned.m8n8.x4.shared.b16 {%0,%1,%2,%3}, [%4];"
                 : "=r"(r0), "=r"(r1), "=r"(r2), "=r"(r3) : "r"(addr));
}
__device__ __forceinline__ void mma16816(float* d, const uint32_t* a, const uint32_t* b) {
    asm volatile("mma.sync.aligned.m16n8k16.row.col.f32.bf16.bf16.f32 "
                 "{%0,%1,%2,%3}, {%4,%5,%6,%7}, {%8,%9}, {%0,%1,%2,%3};"
                 : "+f"(d[0]), "+f"(d[1]), "+f"(d[2]), "+f"(d[3])
                 : "r"(a[0]), "r"(a[1]), "r"(a[2]), "r"(a[3]), "r"(b[0]), "r"(b[1]));
}
__device__ __forceinline__ float2 bf2f(uint32_t u) {
    __nv_bfloat162 h = *reinterpret_cast<__nv_bfloat162*>(&u);
    return __bfloat1622float2(h);
}
// packed f32x2 (base PTX, sm_100+, no arch-specific suffix)
#define PACKF2(out, lo, hi) asm("mov.b64 %0, {%1, %2};" : "=l"(out) : "f"(lo), "f"(hi))
#define UNPACKF2(lo, hi, in) asm("mov.b64 {%0, %1}, %2;" : "=f"(lo), "=f"(hi) : "l"(in))
#define MUL2(d, a, b)    asm("mul.rn.f32x2 %0, %1, %2;" : "=l"(d) : "l"(a), "l"(b))
#define FMA2(d, a, b, c) asm("fma.rn.f32x2 %0, %1, %2, %3;" : "=l"(d) : "l"(a), "l"(b), "l"(c))

// ---------------- weights fp32 -> bf16 (concat layout) -----------------------
__global__ void conv_w_kernel(const float* __restrict__ wk, const float* __restrict__ wv,
                              const float* __restrict__ bk, const float* __restrict__ bv,
                              __nv_bfloat16* __restrict__ w16, float* __restrict__ bias)
{
    int i = blockIdx.x * 256 + threadIdx.x;   // 0..65535
    w16[i]             = __float2bfloat16(wk[i]);
    w16[i + D * D]     = __float2bfloat16(wv[i]);
    if (i < D) { bias[i] = bk[i]; bias[i + D] = bv[i]; }
}

// ---------------- LayerNorm fp32 -> bf16 (big input) -------------------------
__global__ void ln_rows_bf16_kernel(const float* __restrict__ in, __nv_bfloat16* __restrict__ out,
                                    const float* __restrict__ gamma, const float* __restrict__ beta)
{
    int gw   = (blockIdx.x * blockDim.x + threadIdx.x) >> 5;
    int lane = threadIdx.x & 31;
    const float* row = in + (size_t)gw * D;
    float4 a = *(const float4*)(row + lane * 4);
    float4 b = *(const float4*)(row + 128 + lane * 4);
    float s  = a.x + a.y + a.z + a.w + b.x + b.y + b.z + b.w;
    float s2 = a.x*a.x + a.y*a.y + a.z*a.z + a.w*a.w
             + b.x*b.x + b.y*b.y + b.z*b.z + b.w*b.w;
#pragma unroll
    for (int off = 16; off; off >>= 1) {
        s  += __shfl_xor_sync(0xffffffffu, s,  off);
        s2 += __shfl_xor_sync(0xffffffffu, s2, off);
    }
    float mean = s * (1.0f / 256.0f);
    float var  = s2 * (1.0f / 256.0f) - mean * mean;
    float rstd = rsqrtf(var + 1e-5f);
    float4 g0 = *(const float4*)(gamma + lane * 4);
    float4 g1 = *(const float4*)(gamma + 128 + lane * 4);
    float4 e0 = *(const float4*)(beta + lane * 4);
    float4 e1 = *(const float4*)(beta + 128 + lane * 4);
    __nv_bfloat162 p[4];
    p[0] = __float22bfloat162_rn(make_float2((a.x - mean) * rstd * g0.x + e0.x,
                                             (a.y - mean) * rstd * g0.y + e0.y));
    p[1] = __float22bfloat162_rn(make_float2((a.z - mean) * rstd * g0.z + e0.z,
                                             (a.w - mean) * rstd * g0.w + e0.w));
    p[2] = __float22bfloat162_rn(make_float2((b.x - mean) * rstd * g1.x + e1.x,
                                             (b.y - mean) * rstd * g1.y + e1.y));
    p[3] = __float22bfloat162_rn(make_float2((b.z - mean) * rstd * g1.z + e1.z,
                                             (b.w - mean) * rstd * g1.w + e1.w));
    __nv_bfloat16* o = out + (size_t)gw * D;
    *(uint2*)(o + lane * 4)       = make_uint2(*(uint32_t*)&p[0], *(uint32_t*)&p[1]);
    *(uint2*)(o + 128 + lane * 4) = make_uint2(*(uint32_t*)&p[2], *(uint32_t*)&p[3]);
}

// ---------------- KV projection: bf16 mma.sync GEMM (round-3 exact) ----------
#define BMT 128
#define BNT 128
#define KV_STAGE 16384                 // bytes per As or Bs stage
#define KV_SMEM  (4 * KV_STAGE)        // 64 KB

__global__ void __launch_bounds__(256) kv_mma_kernel(
    const __nv_bfloat16* __restrict__ A,
    const __nv_bfloat16* __restrict__ W,
    const float* __restrict__ bias,
    __nv_bfloat16* __restrict__ Kout,
    __nv_bfloat16* __restrict__ Vout)
{
    extern __shared__ char smem[];
    const int tid  = threadIdx.x;
    const int lane = tid & 31;
    const int wid  = tid >> 5;
    const int wm   = wid >> 1;
    const int wn   = wid & 1;
    const int bm   = blockIdx.y * BMT;
    const int bn   = blockIdx.x * BNT;
    const uint32_t sb = smem_u32(smem);

    const char* Ag = (const char*)A + (size_t)bm * 512;
    const char* Wg = (const char*)W + (size_t)bn * 512;

    float acc[2][8][4];
#pragma unroll
    for (int mi = 0; mi < 2; mi++)
#pragma unroll
        for (int nj = 0; nj < 8; nj++)
#pragma unroll
            for (int x = 0; x < 4; x++) acc[mi][nj][x] = 0.0f;

#define LOAD_STAGE(kb, st) do {                                               \
        uint32_t abase = sb + (st) * 2 * KV_STAGE;                            \
        uint32_t bbase = abase + KV_STAGE;                                    \
        const char* ag = Ag + (kb) * 128;                                     \
        const char* wg = Wg + (kb) * 128;                                     \
        _Pragma("unroll")                                                     \
        for (int i = 0; i < 4; i++) {                                         \
            int ci = tid + i * 256;                                           \
            int r = ci >> 3, c = ci & 7;                                      \
            cpasync16(abase + r * 128 + ((c ^ (r & 7)) * 16),                 \
                      ag + (size_t)r * 512 + c * 16);                         \
        }                                                                     \
        _Pragma("unroll")                                                     \
        for (int i = 0; i < 4; i++) {                                         \
            int ci = tid + i * 256;                                           \
            int r = ci >> 3, c = ci & 7;                                      \
            cpasync16(bbase + r * 128 + ((c ^ (r & 7)) * 16),                 \
                      wg + (size_t)r * 512 + c * 16);                        \
        }                                                                     \
        CP_COMMIT();                                                          \
    } while (0)

    LOAD_STAGE(0, 0);

#pragma unroll 1
    for (int kb = 0; kb < 4; kb++) {
        if (kb < 3) { LOAD_STAGE(kb + 1, (kb + 1) & 1); CP_WAIT(1); }
        else        { CP_WAIT(0); }
        __syncthreads();

        uint32_t abase = sb + (kb & 1) * 2 * KV_STAGE;
        uint32_t bbase = abase + KV_STAGE;
#pragma unroll
        for (int ks = 0; ks < 4; ks++) {
            uint32_t afr[2][4];
#pragma unroll
            for (int mi = 0; mi < 2; mi++) {
                int row   = wm * 32 + mi * 16 + (lane & 15);
                int chunk = (ks * 2 + (lane >> 4)) ^ (row & 7);
                ldsm_x4(afr[mi][0], afr[mi][1], afr[mi][2], afr[mi][3],
                        abase + row * 128 + chunk * 16);
            }
            uint32_t bfr[8][2];
#pragma unroll
            for (int njp = 0; njp < 4; njp++) {
                int row   = wn * 64 + njp * 16 + ((lane >> 4) & 1) * 8 + (lane & 7);
                int chunk = (ks * 2 + ((lane >> 3) & 1)) ^ (row & 7);
                uint32_t r0, r1, r2, r3;
                ldsm_x4(r0, r1, r2, r3, bbase + row * 128 + chunk * 16);
                bfr[njp * 2][0]     = r0; bfr[njp * 2][1]     = r1;
                bfr[njp * 2 + 1][0] = r2; bfr[njp * 2 + 1][1] = r3;
            }
#pragma unroll
            for (int mi = 0; mi < 2; mi++)
#pragma unroll
                for (int nj = 0; nj < 8; nj++)
                    mma16816(acc[mi][nj], afr[mi], bfr[nj]);
        }
        __syncthreads();
    }

    __nv_bfloat16* outp;
    int cb;
    if (bn < 256) { outp = Kout; cb = bn; } else { outp = Vout; cb = bn - 256; }
#pragma unroll
    for (int mi = 0; mi < 2; mi++) {
        int r0 = bm + wm * 32 + mi * 16 + (lane >> 2);
#pragma unroll
        for (int nj = 0; nj < 8; nj++) {
            int ncol = wn * 64 + nj * 8 + (lane & 3) * 2;
            float2 bs = *(const float2*)&bias[bn + ncol];
            __nv_bfloat162 lo = __float22bfloat162_rn(
                make_float2(acc[mi][nj][0] + bs.x, acc[mi][nj][1] + bs.y));
            __nv_bfloat162 hi = __float22bfloat162_rn(
                make_float2(acc[mi][nj][2] + bs.x, acc[mi][nj][3] + bs.y));
            *(__nv_bfloat162*)(outp + (size_t)r0 * D + cb + ncol)       = lo;
            *(__nv_bfloat162*)(outp + (size_t)(r0 + 8) * D + cb + ncol) = hi;
        }
    }
#undef LOAD_STAGE
}

// ---------------- Small fp32 SGEMM (optionally two problems in one grid) -----
// C[M,N] = A[M,K] @ W[N,K]^T + bias.  blockIdx.x >= halfx selects set 2.
template <int BM, int BN, int BK, int TM, int TN>
__global__ void sgemm_kernel(const float* __restrict__ A, const float* __restrict__ W,
                             const float* __restrict__ bias, float* __restrict__ C,
                             int M, int N, int K, int relu, int accum,
                             const float* __restrict__ A2, const float* __restrict__ W2,
                             const float* __restrict__ bias2, float* __restrict__ C2,
                             int halfx)
{
    constexpr int THREADS = (BM / TM) * (BN / TN);
    __shared__ float As[BK][BM + 4];
    __shared__ float Ws[BK][BN + 4];
    const int tid  = threadIdx.x;
    int bxn = blockIdx.x;
    const float* Au = A; const float* Wu = W; const float* bu = bias; float* Cu = C;
    if (bxn >= halfx) {
        bxn -= halfx; Au = A2; Wu = W2; bu = bias2; Cu = C2;
    }
    const int bm   = blockIdx.y * BM;
    const int bn   = bxn * BN;
    const int tcol = (tid % (BN / TN)) * TN;
    const int trow = (tid / (BN / TN)) * TM;

    float acc[TM][TN];
#pragma unroll
    for (int i = 0; i < TM; i++)
#pragma unroll
        for (int j = 0; j < TN; j++) acc[i][j] = 0.0f;

    for (int k0 = 0; k0 < K; k0 += BK) {
        constexpr int AL = (BM * BK) / (THREADS * 4);
#pragma unroll
        for (int t = 0; t < AL; t++) {
            int idx = (tid + t * THREADS) * 4;
            int r = idx / BK, c = idx % BK;
            float4 val = *(const float4*)&Au[(size_t)(bm + r) * K + k0 + c];
            As[c + 0][r] = val.x; As[c + 1][r] = val.y;
            As[c + 2][r] = val.z; As[c + 3][r] = val.w;
        }
        constexpr int WL = (BN * BK) / (THREADS * 4);
#pragma unroll
        for (int t = 0; t < WL; t++) {
            int idx = (tid + t * THREADS) * 4;
            int r = idx / BK, c = idx % BK;
            float4 val = *(const float4*)&Wu[(size_t)(bn + r) * K + k0 + c];
            Ws[c + 0][r] = val.x; Ws[c + 1][r] = val.y;
            Ws[c + 2][r] = val.z; Ws[c + 3][r] = val.w;
        }
        __syncthreads();
#pragma unroll
        for (int kk = 0; kk < BK; kk++) {
            float a[TM], b[TN];
#pragma unroll
            for (int i = 0; i < TM; i += 4) {
                float4 t4 = *(const float4*)&As[kk][trow + i];
                a[i] = t4.x; a[i + 1] = t4.y; a[i + 2] = t4.z; a[i + 3] = t4.w;
            }
#pragma unroll
            for (int j = 0; j < TN; j += 4) {
                float4 t4 = *(const float4*)&Ws[kk][tcol + j];
                b[j] = t4.x; b[j + 1] = t4.y; b[j + 2] = t4.z; b[j + 3] = t4.w;
            }
#pragma unroll
            for (int i = 0; i < TM; i++)
#pragma unroll
                for (int j = 0; j < TN; j++) acc[i][j] += a[i] * b[j];
        }
        __syncthreads();
    }

#pragma unroll
    for (int i = 0; i < TM; i++) {
        int r = bm + trow + i;
#pragma unroll
        for (int j = 0; j < TN; j += 4) {
            int c = bn + tcol + j;
            float4 o;
            o.x = acc[i][j + 0] + bu[c + 0];
            o.y = acc[i][j + 1] + bu[c + 1];
            o.z = acc[i][j + 2] + bu[c + 2];
            o.w = acc[i][j + 3] + bu[c + 3];
            if (relu) {
                o.x = fmaxf(o.x, 0.0f); o.y = fmaxf(o.y, 0.0f);
                o.z = fmaxf(o.z, 0.0f); o.w = fmaxf(o.w, 0.0f);
            }
            if (accum) {
                float4 old = *(const float4*)&Cu[(size_t)r * N + c];
                o.x += old.x; o.y += old.y; o.z += old.z; o.w += old.w;
            }
            *(float4*)&Cu[(size_t)r * N + c] = o;
        }
    }
}

// ---------------- Fused LN + SGEMM (K = N = 256, BM=BN=64) -------------------
// C[M,256] = LN(A) @ W^T + bias, optional relu.  LN computed per CTA for its
// 64-row slab into smem (weights still staged through smem like sgemm).
#define LNG_AFULL (64 * 260)
#define LNG_AS    (16 * 68)
#define LNG_SMEM  ((LNG_AFULL + 2 * LNG_AS) * 4)   // 75264 B

__global__ void __launch_bounds__(256) lngemm_kernel(
    const float* __restrict__ A, const float* __restrict__ W,
    const float* __restrict__ bias, float* __restrict__ C,
    const float* __restrict__ gamma, const float* __restrict__ beta, int relu)
{
    extern __shared__ float sm[];
    float* Afull = sm;                    // [64][260]
    float* As    = sm + LNG_AFULL;        // [16][68]
    float* Ws    = As + LNG_AS;           // [16][68]
    const int tid  = threadIdx.x;
    const int wid  = tid >> 5;
    const int lane = tid & 31;
    const int bm   = blockIdx.y * 64;
    const int bn   = blockIdx.x * 64;

    // LN preamble: warp w normalizes rows bm + w*8 .. +7 into Afull
    float4 g0 = *(const float4*)(gamma + lane * 4);
    float4 g1 = *(const float4*)(gamma + 128 + lane * 4);
    float4 e0 = *(const float4*)(beta + lane * 4);
    float4 e1 = *(const float4*)(beta + 128 + lane * 4);
#pragma unroll 1
    for (int j = 0; j < 8; j++) {
        int lr = wid * 8 + j;
        const float* row = A + (size_t)(bm + lr) * D;
        float4 a = *(const float4*)(row + lane * 4);
        float4 c = *(const float4*)(row + 128 + lane * 4);
        float s  = a.x + a.y + a.z + a.w + c.x + c.y + c.z + c.w;
        float s2 = a.x*a.x + a.y*a.y + a.z*a.z + a.w*a.w
                 + c.x*c.x + c.y*c.y + c.z*c.z + c.w*c.w;
#pragma unroll
        for (int off = 16; off; off >>= 1) {
            s  += __shfl_xor_sync(0xffffffffu, s,  off);
            s2 += __shfl_xor_sync(0xffffffffu, s2, off);
        }
        float mean = s * (1.0f / 256.0f);
        float rstd = rsqrtf(s2 * (1.0f / 256.0f) - mean * mean + 1e-5f);
        float4 o0, o1;
        o0.x = (a.x - mean) * rstd * g0.x + e0.x;
        o0.y = (a.y - mean) * rstd * g0.y + e0.y;
        o0.z = (a.z - mean) * rstd * g0.z + e0.z;
        o0.w = (a.w - mean) * rstd * g0.w + e0.w;
        o1.x = (c.x - mean) * rstd * g1.x + e1.x;
        o1.y = (c.y - mean) * rstd * g1.y + e1.y;
        o1.z = (c.z - mean) * rstd * g1.z + e1.z;
        o1.w = (c.w - mean) * rstd * g1.w + e1.w;
        *(float4*)&Afull[lr * 260 + lane * 4]       = o0;
        *(float4*)&Afull[lr * 260 + 128 + lane * 4] = o1;
    }
    __syncthreads();

    // GEMM: 16x16 thread tile grid, TM=TN=4
    const int tcol = (tid & 15) * 4;
    const int trow = (tid >> 4) * 4;
    float acc[4][4];
#pragma unroll
    for (int i = 0; i < 4; i++)
#pragma unroll
        for (int j = 0; j < 4; j++) acc[i][j] = 0.0f;

    for (int k0 = 0; k0 < D; k0 += 16) {
        {
            int idx = tid * 4;
            int r = idx >> 4, c = idx & 15;
            float4 val = *(const float4*)&Afull[r * 260 + k0 + c];
            As[(c + 0) * 68 + r] = val.x; As[(c + 1) * 68 + r] = val.y;
            As[(c + 2) * 68 + r] = val.z; As[(c + 3) * 68 + r] = val.w;
            float4 wv = *(const float4*)&W[(size_t)(bn + r) * D + k0 + c];
            Ws[(c + 0) * 68 + r] = wv.x; Ws[(c + 1) * 68 + r] = wv.y;
            Ws[(c + 2) * 68 + r] = wv.z; Ws[(c + 3) * 68 + r] = wv.w;
        }
        __syncthreads();
#pragma unroll
        for (int kk = 0; kk < 16; kk++) {
            float4 a4 = *(const float4*)&As[kk * 68 + trow];
            float4 b4 = *(const float4*)&Ws[kk * 68 + tcol];
            float av[4] = {a4.x, a4.y, a4.z, a4.w};
            float bv[4] = {b4.x, b4.y, b4.z, b4.w};
#pragma unroll
            for (int i = 0; i < 4; i++)
#pragma unroll
                for (int j = 0; j < 4; j++) acc[i][j] += av[i] * bv[j];
        }
        __syncthreads();
    }

#pragma unroll
    for (int i = 0; i < 4; i++) {
        int r = bm + trow + i;
        int c = bn + tcol;
        float4 o;
        o.x = acc[i][0] + bias[c + 0];
        o.y = acc[i][1] + bias[c + 1];
        o.z = acc[i][2] + bias[c + 2];
        o.w = acc[i][3] + bias[c + 3];
        if (relu) {
            o.x = fmaxf(o.x, 0.0f); o.y = fmaxf(o.y, 0.0f);
            o.z = fmaxf(o.z, 0.0f); o.w = fmaxf(o.w, 0.0f);
        }
        *(float4*)&C[(size_t)r * D + c] = o;
    }
}

// ---------------- Fused attention pass (bf16 k/v, f32x2, in-CTA reduce) ------
__global__ void __launch_bounds__(256) attn_pass_kernel(
    const float* __restrict__ q,
    const __nv_bfloat16* __restrict__ k,
    const __nv_bfloat16* __restrict__ v,
    float* __restrict__ pnum,
    float* __restrict__ pden)
{
    extern __shared__ float sred[];          // 8*2048 floats + 64 den
    const int b    = blockIdx.y;
    const int wid  = threadIdx.x >> 5;
    const int lane = threadIdx.x & 31;
    const int tid  = threadIdx.x;
    const int wg   = blockIdx.x * 8 + wid;   // 0..63
    const float scale = 0.0625f;

    // q packed as f32x2 pairs, pre-scaled
    unsigned long long qp[8][4];
    const float* qb = q + b * S * D;
#pragma unroll
    for (int i = 0; i < 8; i++) {
        float4 q0 = *(const float4*)(qb + i * D + lane * 8);
        float4 q1 = *(const float4*)(qb + i * D + lane * 8 + 4);
        PACKF2(qp[i][0], q0.x * scale, q0.y * scale);
        PACKF2(qp[i][1], q0.z * scale, q0.w * scale);
        PACKF2(qp[i][2], q1.x * scale, q1.y * scale);
        PACKF2(qp[i][3], q1.z * scale, q1.w * scale);
    }

    unsigned long long acc2[8][4];
#pragma unroll
    for (int i = 0; i < 8; i++)
#pragma unroll
        for (int j = 0; j < 4; j++) acc2[i][j] = 0ULL;   // (0.0f, 0.0f)
    float den[8] = {0, 0, 0, 0, 0, 0, 0, 0};

    const size_t base = (size_t)b * NTOK * D;
    const __nv_bfloat16* kb = k + base;
    const __nv_bfloat16* vb = v + base;

    int n = wg;
    uint4 ku = *(const uint4*)(kb + (size_t)n * D + lane * 8);
    uint4 vu = *(const uint4*)(vb + (size_t)n * D + lane * 8);

#pragma unroll 1
    for (int t = 0; t < 64; t++) {
        uint4 nku = ku, nvu = vu;
        int nn = n + 64;
        if (t < 63) {
            nku = *(const uint4*)(kb + (size_t)nn * D + lane * 8);
            nvu = *(const uint4*)(vb + (size_t)nn * D + lane * 8);
        }

        unsigned long long kp[4];
        { float2 f;
          f = bf2f(ku.x); PACKF2(kp[0], f.x, f.y);
          f = bf2f(ku.y); PACKF2(kp[1], f.x, f.y);
          f = bf2f(ku.z); PACKF2(kp[2], f.x, f.y);
          f = bf2f(ku.w); PACKF2(kp[3], f.x, f.y); }

        float dot[8];
#pragma unroll
        for (int i = 0; i < 8; i++) {
            unsigned long long t2;
            MUL2(t2, qp[i][0], kp[0]);
            FMA2(t2, qp[i][1], kp[1], t2);
            FMA2(t2, qp[i][2], kp[2], t2);
            FMA2(t2, qp[i][3], kp[3], t2);
            float lo, hi; UNPACKF2(lo, hi, t2);
            dot[i] = lo + hi;
        }
#pragma unroll
        for (int off = 16; off; off >>= 1)
#pragma unroll
            for (int i = 0; i < 8; i++)
                dot[i] += __shfl_xor_sync(0xffffffffu, dot[i], off);

        // softmax over slots (no max-subtract: |dot| ~ O(6), exp safe in fp32)
        float e[8]; float ssum = 0.0f;
#pragma unroll
        for (int i = 0; i < 8; i++) { e[i] = exp2f(dot[i] * 1.44269504f); ssum += e[i]; }
        float inv = 1.0f / ssum;

        unsigned long long vp[4];
        { float2 f;
          f = bf2f(vu.x); PACKF2(vp[0], f.x, f.y);
          f = bf2f(vu.y); PACKF2(vp[1], f.x, f.y);
          f = bf2f(vu.z); PACKF2(vp[2], f.x, f.y);
          f = bf2f(vu.w); PACKF2(vp[3], f.x, f.y); }
#pragma unroll
        for (int i = 0; i < 8; i++) {
            float a = e[i] * inv + 1e-8f;
            den[i] += a;
            unsigned long long aa; PACKF2(aa, a, a);
            FMA2(acc2[i][0], aa, vp[0], acc2[i][0]);
            FMA2(acc2[i][1], aa, vp[1], acc2[i][1]);
            FMA2(acc2[i][2], aa, vp[2], acc2[i][2]);
            FMA2(acc2[i][3], aa, vp[3], acc2[i][3]);
        }

        n = nn; ku = nku; vu = nvu;
    }

    // in-CTA reduce across 8 warps
    float* sA = sred;
    float* sD = sred + 8 * 2048;
#pragma unroll
    for (int i = 0; i < 8; i++) {
        float a0, a1, a2, a3, a4, a5, a6, a7;
        UNPACKF2(a0, a1, acc2[i][0]); UNPACKF2(a2, a3, acc2[i][1]);
        UNPACKF2(a4, a5, acc2[i][2]); UNPACKF2(a6, a7, acc2[i][3]);
        *(float4*)(sA + wid * 2048 + i * 256 + lane * 8)     = make_float4(a0, a1, a2, a3);
        *(float4*)(sA + wid * 2048 + i * 256 + lane * 8 + 4) = make_float4(a4, a5, a6, a7);
    }
    if (lane == 0) {
#pragma unroll
        for (int i = 0; i < 8; i++) sD[wid * 8 + i] = den[i];
    }
    __syncthreads();

    float* pn = pnum + ((size_t)b * PRED + blockIdx.x) * S * D;
#pragma unroll
    for (int r = 0; r < 8; r++) {
        int idx = tid + r * 256;
        float s = 0.0f;
#pragma unroll
        for (int w = 0; w < 8; w++) s += sA[w * 2048 + idx];
        pn[idx] = s;
    }
    if (tid < 8) {
        float s = 0.0f;
#pragma unroll
        for (int w = 0; w < 8; w++) s += sD[w * 8 + tid];
        pden[(b * PRED + blockIdx.x) * S + tid] = s;
    }
}

__global__ void attn_reduce_kernel(const float* __restrict__ pnum,
                                   const float* __restrict__ pden,
                                   float* __restrict__ upd)
{
    int idx = blockIdx.x * blockDim.x + threadIdx.x;  // over 64*2048
    int b = idx >> 11;
    int i = (idx >> 8) & 7;
    float s = 0.0f, d = 0.0f;
#pragma unroll
    for (int w = 0; w < PRED; w++) {
        s += pnum[((size_t)b * PRED + w) * S * D + (idx & 2047)];
        d += pden[(b * PRED + w) * S + i];
    }
    upd[idx] = s / d;
}

// ---------------- GRU pointwise (torch gate order r,z,n) ---------------------
__global__ void gru_kernel(const float* __restrict__ gx, const float* __restrict__ gh,
                           float* __restrict__ slots)
{
    int idx = blockIdx.x * blockDim.x + threadIdx.x;  // over 512*256
    int row = idx >> 8, d = idx & 255;
    const float* gxr = gx + row * 3 * D;
    const float* ghr = gh + row * 3 * D;
    float xr = gxr[d], xz = gxr[D + d], xn = gxr[2 * D + d];
    float hr = ghr[d], hz = ghr[D + d], hn = ghr[2 * D + d];
    float r = 1.0f / (1.0f + expf(-(xr + hr)));
    float z = 1.0f / (1.0f + expf(-(xz + hz)));
    float nv = tanhf(xn + r * hn);
    float prev = slots[idx];
    slots[idx] = (1.0f - z) * nv + z * prev;
}

// ---------------- host orchestration ----------------------------------------
extern "C" void kernel_launch(void* const* d_in, const int* in_sizes, int n_in,
                              void* d_out, int out_size)
{
    const float* inputs     = (const float*)d_in[0];
    const float* init_slots = (const float*)d_in[1];
    const float* wq   = (const float*)d_in[2];  const float* bq   = (const float*)d_in[3];
    const float* wk   = (const float*)d_in[4];  const float* bk   = (const float*)d_in[5];
    const float* wv   = (const float*)d_in[6];  const float* bv   = (const float*)d_in[7];
    const float* w_ih = (const float*)d_in[8];  const float* b_ih = (const float*)d_in[9];
    const float* w_hh = (const float*)d_in[10]; const float* b_hh = (const float*)d_in[11];
    const float* w1   = (const float*)d_in[12]; const float* b1   = (const float*)d_in[13];
    const float* w2   = (const float*)d_in[14]; const float* b2   = (const float*)d_in[15];
    const float* gin  = (const float*)d_in[16]; const float* bin  = (const float*)d_in[17];
    const float* gsl  = (const float*)d_in[18]; const float* bsl  = (const float*)d_in[19];
    const float* gff  = (const float*)d_in[20]; const float* bff  = (const float*)d_in[21];

    __nv_bfloat16 *xln16, *k16, *v16, *w16;
    float *bias, *slots, *qb, *upd, *hb, *gx, *gh, *pnum, *pden;
    cudaGetSymbolAddress((void**)&xln16, g_xln16);
    cudaGetSymbolAddress((void**)&k16,   g_k16);
    cudaGetSymbolAddress((void**)&v16,   g_v16);
    cudaGetSymbolAddress((void**)&w16,   g_w16);
    cudaGetSymbolAddress((void**)&bias,  g_bias);
    cudaGetSymbolAddress((void**)&slots, g_slots);
    cudaGetSymbolAddress((void**)&qb,    g_qbuf);
    cudaGetSymbolAddress((void**)&upd,   g_upd);
    cudaGetSymbolAddress((void**)&hb,    g_hbuf);
    cudaGetSymbolAddress((void**)&gx,    g_gx);
    cudaGetSymbolAddress((void**)&gh,    g_gh);
    cudaGetSymbolAddress((void**)&pnum,  g_pnum);
    cudaGetSymbolAddress((void**)&pden,  g_pden);

    cudaFuncSetAttribute(kv_mma_kernel, cudaFuncAttributeMaxDynamicSharedMemorySize, KV_SMEM);
    const int ATTN_SMEM = (8 * 2048 + 64) * sizeof(float);
    cudaFuncSetAttribute(attn_pass_kernel, cudaFuncAttributeMaxDynamicSharedMemorySize, ATTN_SMEM);
    cudaFuncSetAttribute(lngemm_kernel, cudaFuncAttributeMaxDynamicSharedMemorySize, LNG_SMEM);

    // prologue
    cudaMemcpyAsync(slots, init_slots, (size_t)ROWS_SLOT * D * sizeof(float),
                    cudaMemcpyDeviceToDevice);
    conv_w_kernel<<<D * D / 256, 256>>>(wk, wv, bk, bv, w16, bias);
    ln_rows_bf16_kernel<<<ROWS_BIG / 8, 256>>>(inputs, xln16, gin, bin);
    kv_mma_kernel<<<dim3(4, ROWS_BIG / BMT), 256, KV_SMEM>>>(xln16, w16, bias, k16, v16);

    for (int it = 0; it < 3; it++) {
        // q = LN(slots) @ wq^T + bq   (fused)
        lngemm_kernel<<<dim3(4, 8), 256, LNG_SMEM>>>(slots, wq, bq, qb, gsl, bsl, 0);
        attn_pass_kernel<<<dim3(PRED, BATCH), 256, ATTN_SMEM>>>(qb, k16, v16, pnum, pden);
        attn_reduce_kernel<<<(BATCH * S * D) / 256, 256>>>(pnum, pden, upd);
        // gx and gh GEMMs in one launch (independent problems, split grid)
        sgemm_kernel<64, 64, 16, 4, 4><<<dim3(24, 8), 256>>>(
            upd, w_ih, b_ih, gx, ROWS_SLOT, 3 * D, D, 0, 0,
            slots, w_hh, b_hh, gh, 12);
        gru_kernel<<<(ROWS_SLOT * D) / 256, 256>>>(gx, gh, slots);
        // h = relu(LN(slots) @ w1^T + b1)   (fused)
        lngemm_kernel<<<dim3(4, 8), 256, LNG_SMEM>>>(slots, w1, b1, hb, gff, bff, 1);
        // slots += h @ w2^T + b2
        sgemm_kernel<64, 64, 16, 4, 4><<<dim3(4, 8), 256>>>(
            hb, w2, b2, slots, ROWS_SLOT, D, D, 0, 1,
            nullptr, nullptr, nullptr, nullptr, 1 << 20);
    }

    cudaMemcpyAsync(d_out, slots, (size_t)ROWS_SLOT * D * sizeof(float),
                    cudaMemcpyDeviceToDevice);
}